// round 15
// baseline (speedup 1.0000x reference)
#include <cuda_runtime.h>
#include <cuda_fp16.h>
#include <cstdint>

#define FEAT 128
#define NCOL 256
#define MAX_NODES 100000
#define BM 64
#define STRIDE_B 272              // bytes per smem row (136 halfs): conflict-free ldmatrix

// Scratch: per-node projected features, fp16 (b1 folded into first half).
__device__ __half g_Ph[(size_t)MAX_NODES * NCOL];

// smem: B0, B1 (128k x 128n fp16, resident), A0, A1 (64m x 128k fp16, double buffer)
#define SB (128 * STRIDE_B)       // 34816 B
#define SAT (64 * STRIDE_B)       // 17408 B
#define OFF_B0 0
#define OFF_B1 (SB)
#define OFF_A0 (2 * SB)
#define OFF_A1 (2 * SB + SAT)
#define SMEM_TOTAL (2 * SB + 2 * SAT)   // 104448 B -> 2 CTAs/SM

__device__ __forceinline__ uint32_t smem_u32(const void* p) {
    uint32_t a;
    asm("{ .reg .u64 t; cvta.to.shared.u64 t, %1; cvt.u32.u64 %0, t; }" : "=r"(a) : "l"(p));
    return a;
}
__device__ __forceinline__ void ldm_x4(uint32_t* r, uint32_t addr) {
    asm volatile("ldmatrix.sync.aligned.m8n8.x4.shared.b16 {%0,%1,%2,%3}, [%4];"
                 : "=r"(r[0]), "=r"(r[1]), "=r"(r[2]), "=r"(r[3]) : "r"(addr));
}
__device__ __forceinline__ void ldm_x4_t(uint32_t* r, uint32_t addr) {
    asm volatile("ldmatrix.sync.aligned.m8n8.x4.trans.shared.b16 {%0,%1,%2,%3}, [%4];"
                 : "=r"(r[0]), "=r"(r[1]), "=r"(r[2]), "=r"(r[3]) : "r"(addr));
}
__device__ __forceinline__ void mma_fp16(float* d, const uint32_t* a, const uint32_t* b) {
    asm volatile(
        "mma.sync.aligned.m16n8k16.row.col.f32.f16.f16.f32 "
        "{%0,%1,%2,%3}, {%4,%5,%6,%7}, {%8,%9}, {%0,%1,%2,%3};"
        : "+f"(d[0]), "+f"(d[1]), "+f"(d[2]), "+f"(d[3])
        : "r"(a[0]), "r"(a[1]), "r"(a[2]), "r"(a[3]), "r"(b[0]), "r"(b[1]));
}
__device__ __forceinline__ uint32_t pack_h2(float a, float b) {
    __half2 t = __floats2half2_rn(a, b);
    return *reinterpret_cast<uint32_t*>(&t);
}

// ---------------------------------------------------------------------------
// Persistent HMMA node GEMM (fp16): P[M,256] = x[M,128] @ Wc[128,256]
// B resident in smem; A double-buffered with prefetch hidden under MMAs.
// Warp tile 32x32: wm=(wid&1)*32, wn=((wid>>1)&3)*32. b1 folded into half 0.
// ---------------------------------------------------------------------------
__global__ void __launch_bounds__(256, 2) node_gemm_hmma(const float* __restrict__ x,
                                                         const float* __restrict__ W1,
                                                         const float* __restrict__ b1,
                                                         int M, int nTiles)
{
    extern __shared__ char smem[];
    const uint32_t sb = smem_u32(smem);
    const int tid  = threadIdx.x;
    const int wid  = tid >> 5;
    const int lane = tid & 31;

    // ---- Fill B (both halves) ONCE: W1 fp32 -> fp16, [k][n] ----
    #pragma unroll 2
    for (int it = tid; it < 128 * 32; it += 256) {
        const int k  = it >> 5;
        const int c4 = (it & 31) << 2;
        float4 v0 = *reinterpret_cast<const float4*>(W1 + (long long)k * FEAT + c4);
        float4 v1 = *reinterpret_cast<const float4*>(W1 + (long long)(FEAT + k) * FEAT + c4);
        *reinterpret_cast<uint2*>(smem + OFF_B0 + k * STRIDE_B + c4 * 2) =
            make_uint2(pack_h2(v0.x, v0.y), pack_h2(v0.z, v0.w));
        *reinterpret_cast<uint2*>(smem + OFF_B1 + k * STRIDE_B + c4 * 2) =
            make_uint2(pack_h2(v1.x, v1.y), pack_h2(v1.z, v1.w));
    }

    // per-thread A-fill geometry: 8 float4 per tile (64x128 elems / 256 thr)
    const int fr = tid >> 5;            // base row 0..7 (+8 per step)
    const int fc4 = (tid & 31) << 2;    // float4 col

    // ---- Prologue: fill A0 for this CTA's first tile ----
    {
        const int mBase = blockIdx.x * BM;
        #pragma unroll
        for (int i = 0; i < 8; ++i) {
            const int r = fr + i * 8;
            float4 v = make_float4(0.f, 0.f, 0.f, 0.f);
            const long long gm = mBase + r;
            if (gm < M) v = *reinterpret_cast<const float4*>(x + gm * FEAT + fc4);
            *reinterpret_cast<uint2*>(smem + OFF_A0 + r * STRIDE_B + fc4 * 2) =
                make_uint2(pack_h2(v.x, v.y), pack_h2(v.z, v.w));
        }
    }
    __syncthreads();

    const int wm = (wid & 1) * 32;
    const int wn = ((wid >> 1) & 3) * 32;
    const int rowIn  = (lane & 7) + ((lane >> 3) & 1) * 8;   // ldmatrix row-in-16
    const int colSel = (lane >> 4) * 8;

    uint32_t cur = 0;

    for (int tile = blockIdx.x; tile < nTiles; tile += gridDim.x) {
        const int mBase = tile * BM;
        const uint32_t offA  = cur ? OFF_A1 : OFF_A0;
        const uint32_t offAn = cur ? OFF_A0 : OFF_A1;

        // ---- Issue prefetch LDGs for the next tile (latency hidden by h=0) ----
        const int tnext = tile + gridDim.x;
        float4 pv[8];
        if (tnext < nTiles) {
            const int nb = tnext * BM;
            #pragma unroll
            for (int i = 0; i < 8; ++i) {
                const int r = fr + i * 8;
                pv[i] = make_float4(0.f, 0.f, 0.f, 0.f);
                const long long gm = nb + r;
                if (gm < M) pv[i] = *reinterpret_cast<const float4*>(x + gm * FEAT + fc4);
            }
        }

        #pragma unroll
        for (int h = 0; h < 2; ++h) {
            const uint32_t offB = (h == 0) ? OFF_B0 : OFF_B1;

            float acc[2][4][4];
            #pragma unroll
            for (int i = 0; i < 2; i++)
                #pragma unroll
                for (int j = 0; j < 4; j++)
                    #pragma unroll
                    for (int q = 0; q < 4; q++) acc[i][j][q] = 0.f;

            #pragma unroll
            for (int ks = 0; ks < 8; ++ks) {
                const int k0 = ks * 16;
                uint32_t ar[2][4], bh[4][2];

                #pragma unroll
                for (int mt = 0; mt < 2; ++mt) {
                    const uint32_t ao = (wm + mt * 16 + rowIn) * STRIDE_B + (k0 + colSel) * 2;
                    ldm_x4(ar[mt], sb + offA + ao);
                }
                #pragma unroll
                for (int np = 0; np < 2; ++np) {
                    const uint32_t bo = (k0 + rowIn) * STRIDE_B + (wn + np * 16 + colSel) * 2;
                    uint32_t th[4];
                    ldm_x4_t(th, sb + offB + bo);
                    bh[2*np][0]   = th[0]; bh[2*np][1]   = th[1];
                    bh[2*np+1][0] = th[2]; bh[2*np+1][1] = th[3];
                }
                #pragma unroll
                for (int mt = 0; mt < 2; ++mt)
                    #pragma unroll
                    for (int nt = 0; nt < 4; ++nt)
                        mma_fp16(acc[mt][nt], ar[mt], bh[nt]);
            }

            // after h=0 compute, drain the prefetch into the spare A buffer
            if (h == 0 && tnext < nTiles) {
                #pragma unroll
                for (int i = 0; i < 8; ++i) {
                    const int r = fr + i * 8;
                    *reinterpret_cast<uint2*>(smem + offAn + r * STRIDE_B + fc4 * 2) =
                        make_uint2(pack_h2(pv[i].x, pv[i].y), pack_h2(pv[i].z, pv[i].w));
                }
            }

            // ---- Epilogue: add b1 (half 0 only), write fp16 P ----
            const bool addB = (h == 0);
            #pragma unroll
            for (int mt = 0; mt < 2; ++mt) {
                const int row0 = mBase + wm + mt * 16 + (lane >> 2);
                #pragma unroll
                for (int nt = 0; nt < 4; ++nt) {
                    const int colLoc = wn + nt * 8 + (lane & 3) * 2;
                    const int col = h * FEAT + colLoc;
                    float bx = 0.f, by = 0.f;
                    if (addB) { bx = b1[colLoc]; by = b1[colLoc + 1]; }
                    if (row0 < M) {
                        __half2 v = __floats2half2_rn(acc[mt][nt][0] + bx, acc[mt][nt][1] + by);
                        *reinterpret_cast<__half2*>(g_Ph + (long long)row0 * NCOL + col) = v;
                    }
                    if (row0 + 8 < M) {
                        __half2 v = __floats2half2_rn(acc[mt][nt][2] + bx, acc[mt][nt][3] + by);
                        *reinterpret_cast<__half2*>(g_Ph + (long long)(row0 + 8) * NCOL + col) = v;
                    }
                }
            }
        }

        __syncthreads();   // prefetch STS visible; safe to read offAn / overwrite offA
        cur ^= 1;
    }
}

// ---------------------------------------------------------------------------
// Edge kernel: 8 lanes per edge, TWO edges per iteration (MLP=8 LDG.128).
// Lane o owns bytes [o*16,+16) of each 128B line -> 1 L1 wavefront per line.
// ---------------------------------------------------------------------------
__global__ __launch_bounds__(256) void edge_kernel(const int* __restrict__ ei32,
                                                   const float* __restrict__ W2,
                                                   const float* __restrict__ b2,
                                                   float* __restrict__ out,
                                                   int E, int nOcts)
{
    const int o   = threadIdx.x & 7;
    const int oct = (blockIdx.x * blockDim.x + threadIdx.x) >> 3;

    float w[16];
    {
        const float4* w4a = reinterpret_cast<const float4*>(W2 + o * 8);
        const float4* w4b = reinterpret_cast<const float4*>(W2 + 64 + o * 8);
        #pragma unroll
        for (int i = 0; i < 2; ++i) {
            float4 v = w4a[i];
            w[i*4+0] = v.x; w[i*4+1] = v.y; w[i*4+2] = v.z; w[i*4+3] = v.w;
            float4 u = w4b[i];
            w[8+i*4+0] = u.x; w[8+i*4+1] = u.y; w[8+i*4+2] = u.z; w[8+i*4+3] = u.w;
        }
    }
    const float bias2 = b2[0];
    const int shift = (ei32[1] | ei32[3] | ei32[5] | ei32[7]) == 0 ? 1 : 0;
    const __half2 z2 = __floats2half2_rn(0.f, 0.f);

    for (int e0 = oct * 2; e0 < E; e0 += 2 * nOcts) {
        const int e1 = e0 + 1;
        const bool has1 = (e1 < E);

        const int r0 = ei32[(long long)e0 << shift];
        const int c0 = ei32[(long long)(E + e0) << shift];
        const int r1 = has1 ? ei32[(long long)e1 << shift] : r0;
        const int c1 = has1 ? ei32[(long long)(E + e1) << shift] : c0;

        const __half* pa0 = g_Ph + (long long)r0 * NCOL;
        const __half* pb0 = g_Ph + (long long)c0 * NCOL + FEAT;
        const __half* pa1 = g_Ph + (long long)r1 * NCOL;
        const __half* pb1 = g_Ph + (long long)c1 * NCOL + FEAT;

        uint4 av0[2], bv0[2], av1[2], bv1[2];
        #pragma unroll
        for (int i = 0; i < 2; ++i) {
            av0[i] = *reinterpret_cast<const uint4*>(pa0 + i * 64 + o * 8);
            bv0[i] = *reinterpret_cast<const uint4*>(pb0 + i * 64 + o * 8);
            av1[i] = *reinterpret_cast<const uint4*>(pa1 + i * 64 + o * 8);
            bv1[i] = *reinterpret_cast<const uint4*>(pb1 + i * 64 + o * 8);
        }

        float acc0 = 0.f, acc1 = 0.f;
        #pragma unroll
        for (int i = 0; i < 2; ++i) {
            const __half2* ah0 = reinterpret_cast<const __half2*>(&av0[i]);
            const __half2* bh0 = reinterpret_cast<const __half2*>(&bv0[i]);
            const __half2* ah1 = reinterpret_cast<const __half2*>(&av1[i]);
            const __half2* bh1 = reinterpret_cast<const __half2*>(&bv1[i]);
            #pragma unroll
            for (int j = 0; j < 4; ++j) {
                __half2 s0 = __hmax2(__hadd2(ah0[j], bh0[j]), z2);
                __half2 s1 = __hmax2(__hadd2(ah1[j], bh1[j]), z2);
                float2 f0 = __half22float2(s0);
                float2 f1 = __half22float2(s1);
                acc0 = fmaf(f0.x, w[i*8 + j*2],     acc0);
                acc0 = fmaf(f0.y, w[i*8 + j*2 + 1], acc0);
                acc1 = fmaf(f1.x, w[i*8 + j*2],     acc1);
                acc1 = fmaf(f1.y, w[i*8 + j*2 + 1], acc1);
            }
        }
        acc0 += __shfl_xor_sync(0xffffffffu, acc0, 1);
        acc1 += __shfl_xor_sync(0xffffffffu, acc1, 1);
        acc0 += __shfl_xor_sync(0xffffffffu, acc0, 2);
        acc1 += __shfl_xor_sync(0xffffffffu, acc1, 2);
        acc0 += __shfl_xor_sync(0xffffffffu, acc0, 4);
        acc1 += __shfl_xor_sync(0xffffffffu, acc1, 4);

        if (o == 0) {
            out[e0] = 1.0f / (1.0f + __expf(-(acc0 + bias2)));
            if (has1) out[e1] = 1.0f / (1.0f + __expf(-(acc1 + bias2)));
        }
    }
}

// ---------------------------------------------------------------------------
extern "C" void kernel_launch(void* const* d_in, const int* in_sizes, int n_in,
                              void* d_out, int out_size)
{
    const float* x   = (const float*)d_in[0];
    const int*   ei  = (const int*)d_in[1];
    const float* W1  = (const float*)d_in[2];
    const float* b1  = (const float*)d_in[3];
    const float* W2  = (const float*)d_in[4];
    const float* b2  = (const float*)d_in[5];
    float* out = (float*)d_out;

    const int M = in_sizes[0] / FEAT;
    const int E = in_sizes[1] / 2;

    static bool attr_set = false;
    if (!attr_set) {
        cudaFuncSetAttribute(node_gemm_hmma, cudaFuncAttributeMaxDynamicSharedMemorySize, SMEM_TOTAL);
        attr_set = true;
    }

    const int nTiles = (M + BM - 1) / BM;
    const int gemmGrid = (nTiles < 296) ? nTiles : 296;   // 2 CTAs/SM persistent
    node_gemm_hmma<<<gemmGrid, 256, SMEM_TOTAL>>>(x, W1, b1, M, nTiles);

    const int blocks = 1184;
    const int nOcts = blocks * (256 / 8);
    edge_kernel<<<blocks, 256>>>(ei, W2, b2, out, E, nOcts);
}

// round 16
// speedup vs baseline: 1.0127x; 1.0127x over previous
#include <cuda_runtime.h>
#include <cuda_fp16.h>
#include <cstdint>

#define FEAT 128
#define NCOL 256
#define MAX_NODES 100000
#define BM 64
#define STRIDE_B 272              // bytes per smem row (136 halfs): conflict-free ldmatrix

// Scratch: per-node projected features, fp16 (b1 folded into first half).
__device__ __half g_Ph[(size_t)MAX_NODES * NCOL];
// Work-stealing ticket (reset to 0 via cudaMemsetAsync before each GEMM launch)
__device__ int g_ticket;

// smem: B0, B1 (128k x 128n fp16, resident), A0, A1 (64m x 128k fp16, double buffer)
#define SB (128 * STRIDE_B)       // 34816 B
#define SAT (64 * STRIDE_B)       // 17408 B
#define OFF_B0 0
#define OFF_B1 (SB)
#define OFF_A0 (2 * SB)
#define OFF_A1 (2 * SB + SAT)
#define SMEM_TOTAL (2 * SB + 2 * SAT)   // 104448 B -> 2 CTAs/SM

__device__ __forceinline__ uint32_t smem_u32(const void* p) {
    uint32_t a;
    asm("{ .reg .u64 t; cvta.to.shared.u64 t, %1; cvt.u32.u64 %0, t; }" : "=r"(a) : "l"(p));
    return a;
}
__device__ __forceinline__ void ldm_x4(uint32_t* r, uint32_t addr) {
    asm volatile("ldmatrix.sync.aligned.m8n8.x4.shared.b16 {%0,%1,%2,%3}, [%4];"
                 : "=r"(r[0]), "=r"(r[1]), "=r"(r[2]), "=r"(r[3]) : "r"(addr));
}
__device__ __forceinline__ void ldm_x4_t(uint32_t* r, uint32_t addr) {
    asm volatile("ldmatrix.sync.aligned.m8n8.x4.trans.shared.b16 {%0,%1,%2,%3}, [%4];"
                 : "=r"(r[0]), "=r"(r[1]), "=r"(r[2]), "=r"(r[3]) : "r"(addr));
}
__device__ __forceinline__ void mma_fp16(float* d, const uint32_t* a, const uint32_t* b) {
    asm volatile(
        "mma.sync.aligned.m16n8k16.row.col.f32.f16.f16.f32 "
        "{%0,%1,%2,%3}, {%4,%5,%6,%7}, {%8,%9}, {%0,%1,%2,%3};"
        : "+f"(d[0]), "+f"(d[1]), "+f"(d[2]), "+f"(d[3])
        : "r"(a[0]), "r"(a[1]), "r"(a[2]), "r"(a[3]), "r"(b[0]), "r"(b[1]));
}
__device__ __forceinline__ uint32_t pack_h2(float a, float b) {
    __half2 t = __floats2half2_rn(a, b);
    return *reinterpret_cast<uint32_t*>(&t);
}

// ---------------------------------------------------------------------------
// Persistent HMMA node GEMM (fp16): P[M,256] = x[M,128] @ Wc[128,256]
// B resident in smem; A double-buffered + prefetched; tiles claimed via
// global atomic ticket (work-stealing kills the 5-vs-6-tile tail).
// ---------------------------------------------------------------------------
__global__ void __launch_bounds__(256, 2) node_gemm_hmma(const float* __restrict__ x,
                                                         const float* __restrict__ W1,
                                                         const float* __restrict__ b1,
                                                         int M, int nTiles)
{
    extern __shared__ char smem[];
    __shared__ int s_nt[2];
    __shared__ int s_first;
    const uint32_t sb = smem_u32(smem);
    const int tid  = threadIdx.x;
    const int wid  = tid >> 5;
    const int lane = tid & 31;

    // ---- Fill B (both halves) ONCE: W1 fp32 -> fp16, [k][n] ----
    #pragma unroll 2
    for (int it = tid; it < 128 * 32; it += 256) {
        const int k  = it >> 5;
        const int c4 = (it & 31) << 2;
        float4 v0 = *reinterpret_cast<const float4*>(W1 + (long long)k * FEAT + c4);
        float4 v1 = *reinterpret_cast<const float4*>(W1 + (long long)(FEAT + k) * FEAT + c4);
        *reinterpret_cast<uint2*>(smem + OFF_B0 + k * STRIDE_B + c4 * 2) =
            make_uint2(pack_h2(v0.x, v0.y), pack_h2(v0.z, v0.w));
        *reinterpret_cast<uint2*>(smem + OFF_B1 + k * STRIDE_B + c4 * 2) =
            make_uint2(pack_h2(v1.x, v1.y), pack_h2(v1.z, v1.w));
    }
    if (tid == 0) {
        s_first = atomicAdd(&g_ticket, 1);
        s_nt[0] = atomicAdd(&g_ticket, 1);
    }
    __syncthreads();

    // per-thread A-fill geometry: 8 float4 per tile (64x128 elems / 256 thr)
    const int fr = tid >> 5;            // base row 0..7 (+8 per step)
    const int fc4 = (tid & 31) << 2;    // float4 col

    int tile = s_first;
    if (tile < nTiles) {
        const int mBase = tile * BM;
        #pragma unroll
        for (int i = 0; i < 8; ++i) {
            const int r = fr + i * 8;
            float4 v = make_float4(0.f, 0.f, 0.f, 0.f);
            const long long gm = mBase + r;
            if (gm < M) v = *reinterpret_cast<const float4*>(x + gm * FEAT + fc4);
            *reinterpret_cast<uint2*>(smem + OFF_A0 + r * STRIDE_B + fc4 * 2) =
                make_uint2(pack_h2(v.x, v.y), pack_h2(v.z, v.w));
        }
    }
    __syncthreads();

    const int wm = (wid & 1) * 32;
    const int wn = ((wid >> 1) & 3) * 32;
    const int rowIn  = (lane & 7) + ((lane >> 3) & 1) * 8;
    const int colSel = (lane >> 4) * 8;

    uint32_t cur = 0;
    int p = 0;

    while (tile < nTiles) {
        const int mBase = tile * BM;
        const uint32_t offA  = cur ? OFF_A1 : OFF_A0;
        const uint32_t offAn = cur ? OFF_A0 : OFF_A1;

        // next tile (published by sync at end of previous iteration)
        const int tnext = s_nt[p];

        // ---- Issue prefetch LDGs for the next tile ----
        float4 pv[8];
        if (tnext < nTiles) {
            const int nb = tnext * BM;
            #pragma unroll
            for (int i = 0; i < 8; ++i) {
                const int r = fr + i * 8;
                pv[i] = make_float4(0.f, 0.f, 0.f, 0.f);
                const long long gm = nb + r;
                if (gm < M) pv[i] = *reinterpret_cast<const float4*>(x + gm * FEAT + fc4);
            }
        }

        #pragma unroll
        for (int h = 0; h < 2; ++h) {
            const uint32_t offB = (h == 0) ? OFF_B0 : OFF_B1;

            float acc[2][4][4];
            #pragma unroll
            for (int i = 0; i < 2; i++)
                #pragma unroll
                for (int j = 0; j < 4; j++)
                    #pragma unroll
                    for (int q = 0; q < 4; q++) acc[i][j][q] = 0.f;

            #pragma unroll
            for (int ks = 0; ks < 8; ++ks) {
                const int k0 = ks * 16;
                uint32_t ar[2][4], bh[4][2];

                #pragma unroll
                for (int mt = 0; mt < 2; ++mt) {
                    const uint32_t ao = (wm + mt * 16 + rowIn) * STRIDE_B + (k0 + colSel) * 2;
                    ldm_x4(ar[mt], sb + offA + ao);
                }
                #pragma unroll
                for (int np = 0; np < 2; ++np) {
                    const uint32_t bo = (k0 + rowIn) * STRIDE_B + (wn + np * 16 + colSel) * 2;
                    uint32_t th[4];
                    ldm_x4_t(th, sb + offB + bo);
                    bh[2*np][0]   = th[0]; bh[2*np][1]   = th[1];
                    bh[2*np+1][0] = th[2]; bh[2*np+1][1] = th[3];
                }
                #pragma unroll
                for (int mt = 0; mt < 2; ++mt)
                    #pragma unroll
                    for (int nt = 0; nt < 4; ++nt)
                        mma_fp16(acc[mt][nt], ar[mt], bh[nt]);
            }

            // after h=0 compute, drain the prefetch into the spare A buffer
            if (h == 0 && tnext < nTiles) {
                #pragma unroll
                for (int i = 0; i < 8; ++i) {
                    const int r = fr + i * 8;
                    *reinterpret_cast<uint2*>(smem + offAn + r * STRIDE_B + fc4 * 2) =
                        make_uint2(pack_h2(pv[i].x, pv[i].y), pack_h2(pv[i].z, pv[i].w));
                }
            }

            // ---- Epilogue: add b1 (half 0 only), write fp16 P ----
            const bool addB = (h == 0);
            #pragma unroll
            for (int mt = 0; mt < 2; ++mt) {
                const int row0 = mBase + wm + mt * 16 + (lane >> 2);
                #pragma unroll
                for (int nt = 0; nt < 4; ++nt) {
                    const int colLoc = wn + nt * 8 + (lane & 3) * 2;
                    const int col = h * FEAT + colLoc;
                    float bx = 0.f, by = 0.f;
                    if (addB) { bx = b1[colLoc]; by = b1[colLoc + 1]; }
                    if (row0 < M) {
                        __half2 v = __floats2half2_rn(acc[mt][nt][0] + bx, acc[mt][nt][1] + by);
                        *reinterpret_cast<__half2*>(g_Ph + (long long)row0 * NCOL + col) = v;
                    }
                    if (row0 + 8 < M) {
                        __half2 v = __floats2half2_rn(acc[mt][nt][2] + bx, acc[mt][nt][3] + by);
                        *reinterpret_cast<__half2*>(g_Ph + (long long)(row0 + 8) * NCOL + col) = v;
                    }
                }
            }
        }

        // fetch the tile-after-next into the slot consumed LAST iteration
        if (tid == 0) s_nt[p ^ 1] = atomicAdd(&g_ticket, 1);
        __syncthreads();   // publishes s_nt write + prefetch STS; protects A swap
        tile = tnext;
        cur ^= 1;
        p ^= 1;
    }
}

// ---------------------------------------------------------------------------
// Edge kernel: 8 lanes per edge, TWO edges per iteration (MLP=8 LDG.128).
// W2 slice held as 8x half2 (reg diet -> 5 blocks/SM). Float accumulation.
// ---------------------------------------------------------------------------
__global__ void __launch_bounds__(256, 5) edge_kernel(const int* __restrict__ ei32,
                                                      const float* __restrict__ W2,
                                                      const float* __restrict__ b2,
                                                      float* __restrict__ out,
                                                      int E, int nOcts)
{
    const int o   = threadIdx.x & 7;
    const int oct = (blockIdx.x * blockDim.x + threadIdx.x) >> 3;

    // W2 slice for this lane: [o*8,+8) and [64+o*8,+8) -> 8 half2 regs
    __half2 wh[8];
    {
        const float4* w4a = reinterpret_cast<const float4*>(W2 + o * 8);
        const float4* w4b = reinterpret_cast<const float4*>(W2 + 64 + o * 8);
        #pragma unroll
        for (int i = 0; i < 2; ++i) {
            float4 v = w4a[i];
            wh[i*2+0] = __floats2half2_rn(v.x, v.y);
            wh[i*2+1] = __floats2half2_rn(v.z, v.w);
            float4 u = w4b[i];
            wh[4+i*2+0] = __floats2half2_rn(u.x, u.y);
            wh[4+i*2+1] = __floats2half2_rn(u.z, u.w);
        }
    }
    const float bias2 = b2[0];
    const int shift = (ei32[1] | ei32[3] | ei32[5] | ei32[7]) == 0 ? 1 : 0;
    const __half2 z2 = __floats2half2_rn(0.f, 0.f);

    for (int e0 = oct * 2; e0 < E; e0 += 2 * nOcts) {
        const int e1 = e0 + 1;
        const bool has1 = (e1 < E);

        const int r0 = ei32[(long long)e0 << shift];
        const int c0 = ei32[(long long)(E + e0) << shift];
        const int r1 = has1 ? ei32[(long long)e1 << shift] : r0;
        const int c1 = has1 ? ei32[(long long)(E + e1) << shift] : c0;

        const __half* pa0 = g_Ph + (long long)r0 * NCOL;
        const __half* pb0 = g_Ph + (long long)c0 * NCOL + FEAT;
        const __half* pa1 = g_Ph + (long long)r1 * NCOL;
        const __half* pb1 = g_Ph + (long long)c1 * NCOL + FEAT;

        uint4 av0[2], bv0[2], av1[2], bv1[2];
        #pragma unroll
        for (int i = 0; i < 2; ++i) {
            av0[i] = *reinterpret_cast<const uint4*>(pa0 + i * 64 + o * 8);
            bv0[i] = *reinterpret_cast<const uint4*>(pb0 + i * 64 + o * 8);
            av1[i] = *reinterpret_cast<const uint4*>(pa1 + i * 64 + o * 8);
            bv1[i] = *reinterpret_cast<const uint4*>(pb1 + i * 64 + o * 8);
        }

        float acc0 = 0.f, acc1 = 0.f;
        #pragma unroll
        for (int i = 0; i < 2; ++i) {
            const __half2* ah0 = reinterpret_cast<const __half2*>(&av0[i]);
            const __half2* bh0 = reinterpret_cast<const __half2*>(&bv0[i]);
            const __half2* ah1 = reinterpret_cast<const __half2*>(&av1[i]);
            const __half2* bh1 = reinterpret_cast<const __half2*>(&bv1[i]);
            #pragma unroll
            for (int j = 0; j < 4; ++j) {
                const float2 wf = __half22float2(wh[i*4 + j]);
                __half2 s0 = __hmax2(__hadd2(ah0[j], bh0[j]), z2);
                __half2 s1 = __hmax2(__hadd2(ah1[j], bh1[j]), z2);
                float2 f0 = __half22float2(s0);
                float2 f1 = __half22float2(s1);
                acc0 = fmaf(f0.x, wf.x, acc0);
                acc0 = fmaf(f0.y, wf.y, acc0);
                acc1 = fmaf(f1.x, wf.x, acc1);
                acc1 = fmaf(f1.y, wf.y, acc1);
            }
        }
        acc0 += __shfl_xor_sync(0xffffffffu, acc0, 1);
        acc1 += __shfl_xor_sync(0xffffffffu, acc1, 1);
        acc0 += __shfl_xor_sync(0xffffffffu, acc0, 2);
        acc1 += __shfl_xor_sync(0xffffffffu, acc1, 2);
        acc0 += __shfl_xor_sync(0xffffffffu, acc0, 4);
        acc1 += __shfl_xor_sync(0xffffffffu, acc1, 4);

        if (o == 0) {
            out[e0] = 1.0f / (1.0f + __expf(-(acc0 + bias2)));
            if (has1) out[e1] = 1.0f / (1.0f + __expf(-(acc1 + bias2)));
        }
    }
}

// ---------------------------------------------------------------------------
extern "C" void kernel_launch(void* const* d_in, const int* in_sizes, int n_in,
                              void* d_out, int out_size)
{
    const float* x   = (const float*)d_in[0];
    const int*   ei  = (const int*)d_in[1];
    const float* W1  = (const float*)d_in[2];
    const float* b1  = (const float*)d_in[3];
    const float* W2  = (const float*)d_in[4];
    const float* b2  = (const float*)d_in[5];
    float* out = (float*)d_out;

    const int M = in_sizes[0] / FEAT;
    const int E = in_sizes[1] / 2;

    static bool init_done = false;
    static void* ticket_ptr = nullptr;
    if (!init_done) {
        cudaFuncSetAttribute(node_gemm_hmma, cudaFuncAttributeMaxDynamicSharedMemorySize, SMEM_TOTAL);
        cudaGetSymbolAddress(&ticket_ptr, g_ticket);
        init_done = true;
    }

    // reset the work-stealing ticket (async, graph-capturable)
    cudaMemsetAsync(ticket_ptr, 0, sizeof(int));

    const int nTiles = (M + BM - 1) / BM;
    const int gemmGrid = (nTiles < 296) ? nTiles : 296;   // 2 CTAs/SM persistent
    node_gemm_hmma<<<gemmGrid, 256, SMEM_TOTAL>>>(x, W1, b1, M, nTiles);

    const int blocks = 740;                               // 148 SMs x 5 blocks, one wave
    const int nOcts = blocks * (256 / 8);
    edge_kernel<<<blocks, 256>>>(ei, W2, b2, out, E, nOcts);
}